// round 11
// baseline (speedup 1.0000x reference)
#include <cuda_runtime.h>
#include <cuda_bf16.h>
#include <cuda_fp16.h>
#include <cstdint>
#include <math.h>

#define B_  4
#define T_  2048
#define C_  1024
#define NH_ 16
#define HD_ 64
#define M_  (B_*T_)   // 8192 rows

// ---- scratch (static __device__ arrays: allocation-free) ----
static __device__ float g_q[B_*NH_*T_*HD_];    // [b][h][t][d]
static __device__ float g_k[B_*NH_*T_*HD_];
static __device__ float g_v[B_*NH_*T_*HD_];
static __device__ float g_cos[T_*32];
static __device__ float g_sin[T_*32];
static __device__ __nv_bfloat16 g_ahi[M_*C_];    // x split hi  [m][k]
static __device__ __nv_bfloat16 g_alo[M_*C_];    // x split lo
static __device__ __nv_bfloat16 g_atthi[M_*C_];  // attn out split hi [m][h*64+d]
static __device__ __nv_bfloat16 g_attlo[M_*C_];
static __device__ __nv_bfloat16 g_bhi[3*C_*C_];  // W transposed [N][K] hi
static __device__ __nv_bfloat16 g_blo[3*C_*C_];  // W transposed [N][K] lo

// ============================================================
// helpers (baseline PTX only: works on generic compute_103)
// ============================================================
__device__ __forceinline__ uint32_t smem_u32(const void* p) {
    uint32_t a;
    asm("{ .reg .u64 t; cvta.to.shared.u64 t, %1; cvt.u32.u64 %0, t; }"
        : "=r"(a) : "l"(p));
    return a;
}
__device__ __forceinline__ void cpasync16(uint32_t dst, const void* src) {
    asm volatile("cp.async.ca.shared.global [%0], [%1], 16;"
                 :: "r"(dst), "l"(__cvta_generic_to_global(src)));
}
#define CP_COMMIT() asm volatile("cp.async.commit_group;" ::: "memory")
#define CP_WAIT1()  asm volatile("cp.async.wait_group 1;" ::: "memory")
#define CP_WAIT0()  asm volatile("cp.async.wait_group 0;" ::: "memory")

__device__ __forceinline__ void ldsm4(uint32_t* r, uint32_t addr) {
    asm volatile("ldmatrix.sync.aligned.m8n8.x4.shared.b16 {%0,%1,%2,%3}, [%4];"
                 : "=r"(r[0]), "=r"(r[1]), "=r"(r[2]), "=r"(r[3]) : "r"(addr));
}
__device__ __forceinline__ void ldsm2(uint32_t* r, uint32_t addr) {
    asm volatile("ldmatrix.sync.aligned.m8n8.x2.shared.b16 {%0,%1}, [%2];"
                 : "=r"(r[0]), "=r"(r[1]) : "r"(addr));
}
__device__ __forceinline__ void ldsm2t(uint32_t* r, uint32_t addr) {
    asm volatile("ldmatrix.sync.aligned.m8n8.x2.trans.shared.b16 {%0,%1}, [%2];"
                 : "=r"(r[0]), "=r"(r[1]) : "r"(addr));
}
__device__ __forceinline__ void mma_bf16(float* c, const uint32_t* a, const uint32_t* b) {
    asm volatile("mma.sync.aligned.m16n8k16.row.col.f32.bf16.bf16.f32 "
                 "{%0,%1,%2,%3}, {%4,%5,%6,%7}, {%8,%9}, {%0,%1,%2,%3};"
                 : "+f"(c[0]), "+f"(c[1]), "+f"(c[2]), "+f"(c[3])
                 : "r"(a[0]), "r"(a[1]), "r"(a[2]), "r"(a[3]),
                   "r"(b[0]), "r"(b[1]));
}
__device__ __forceinline__ void mma_f16(float* c, const uint32_t* a, const uint32_t* b) {
    asm volatile("mma.sync.aligned.m16n8k16.row.col.f32.f16.f16.f32 "
                 "{%0,%1,%2,%3}, {%4,%5,%6,%7}, {%8,%9}, {%0,%1,%2,%3};"
                 : "+f"(c[0]), "+f"(c[1]), "+f"(c[2]), "+f"(c[3])
                 : "r"(a[0]), "r"(a[1]), "r"(a[2]), "r"(a[3]),
                   "r"(b[0]), "r"(b[1]));
}
__device__ __forceinline__ uint32_t pk2(__nv_bfloat16 a, __nv_bfloat16 b) {
    __nv_bfloat162 t; t.x = a; t.y = b;
    return *reinterpret_cast<uint32_t*>(&t);
}
__device__ __forceinline__ uint32_t pkh2(float a, float b) {
    __half2 t = __floats2half2_rn(a, b);
    return *reinterpret_cast<uint32_t*>(&t);
}

// ============================================================
// RoPE tables (fp64 once -> fp32 tables)
// ============================================================
__global__ void rope_table_kernel()
{
    int idx = blockIdx.x * blockDim.x + threadIdx.x;
    if (idx >= T_ * 32) return;
    int t = idx >> 5, i = idx & 31;
    double inv = pow(10000.0, -(double)i / 32.0);
    double ang = (double)t * inv;
    g_cos[idx] = (float)cos(ang);
    g_sin[idx] = (float)sin(ang);
}

// ============================================================
// x -> bf16 hi/lo split (row-major [m][k])
// ============================================================
__global__ __launch_bounds__(256)
void xconv_kernel(const float* __restrict__ x)
{
    int idx = blockIdx.x * 256 + threadIdx.x;   // over M_*C_/4
    float4 v = reinterpret_cast<const float4*>(x)[idx];
    __nv_bfloat16 h0 = __float2bfloat16(v.x);
    __nv_bfloat16 h1 = __float2bfloat16(v.y);
    __nv_bfloat16 h2 = __float2bfloat16(v.z);
    __nv_bfloat16 h3 = __float2bfloat16(v.w);
    uint2 hi = make_uint2(pk2(h0, h1), pk2(h2, h3));
    uint2 lo = make_uint2(
        pk2(__float2bfloat16(v.x - __bfloat162float(h0)),
            __float2bfloat16(v.y - __bfloat162float(h1))),
        pk2(__float2bfloat16(v.z - __bfloat162float(h2)),
            __float2bfloat16(v.w - __bfloat162float(h3))));
    reinterpret_cast<uint2*>(g_ahi)[idx] = hi;
    reinterpret_cast<uint2*>(g_alo)[idx] = lo;
}

// ============================================================
// W transpose + bf16 hi/lo split: g_b{hi,lo}[n][k] = split(W[k][n])
// ============================================================
__global__ __launch_bounds__(256)
void wconv_kernel(const float* __restrict__ W, int N)
{
    __shared__ float s[32][33];
    const int kb = blockIdx.y * 32, nb = blockIdx.x * 32;
    const int tx = threadIdx.x, ty = threadIdx.y;   // 32 x 8
#pragma unroll
    for (int j = 0; j < 4; j++)
        s[ty * 4 + j][tx] = W[(kb + ty * 4 + j) * N + nb + tx];
    __syncthreads();
#pragma unroll
    for (int j = 0; j < 4; j++) {
        float v = s[tx][ty * 4 + j];
        __nv_bfloat16 h = __float2bfloat16(v);
        float lo = v - __bfloat162float(h);
        int idx = (nb + ty * 4 + j) * C_ + kb + tx;
        g_bhi[idx] = h;
        g_blo[idx] = __float2bfloat16(lo);
    }
}

// ============================================================
// bf16 mma.sync GEMM v2: block 128x256, 8 warps (2m x 4n),
//   warp tile 64x64, BK=32, 2-stage cp.async, paired ldsm4 for B.
//   MODE 0: scatter into g_q/g_k/g_v with FUSED RoPE on q,k
//   MODE 1: A := g_atthi/lo, write fp32 out + bias
// ============================================================
static constexpr int RS2     = 80;            // row stride bytes (64 + 16 pad)
static constexpr int SA2_HI  = 0;             // 128 rows
static constexpr int SA2_LO  = 10240;
static constexpr int SB2_HI  = 20480;         // 256 rows
static constexpr int SB2_LO  = 40960;
static constexpr int STAGE2  = 61440;
static constexpr int SMEM_SZ2 = 2 * STAGE2;   // 122880

template<int N, int MODE>
__global__ __launch_bounds__(256)
void mma_gemm_kernel(const float* __restrict__ bias, float* __restrict__ out)
{
    extern __shared__ __align__(128) char smem[];
    const uint32_t sb = smem_u32(smem);
    const int tid = threadIdx.x, lane = tid & 31, wid = tid >> 5;
    const int wm = wid >> 2, wn = wid & 3;
    const int m0 = blockIdx.y * 128, n0 = blockIdx.x * 256;

    const __nv_bfloat16* Ah = (MODE == 0) ? g_ahi : g_atthi;
    const __nv_bfloat16* Al = (MODE == 0) ? g_alo : g_attlo;

    float acc[4][8][4];
#pragma unroll
    for (int a = 0; a < 4; a++)
#pragma unroll
        for (int b = 0; b < 8; b++)
#pragma unroll
            for (int c = 0; c < 4; c++) acc[a][b][c] = 0.f;

    auto prefetch = [&](int chunk) {
        const int k0 = chunk * 32;
        const uint32_t sbase = sb + (chunk & 1) * STAGE2;
        // A: 1024 tasks (hi 512 + lo 512), 16B each
#pragma unroll
        for (int i = 0; i < 4; i++) {
            int p = tid + i * 256;
            int sel = p >> 9, q = p & 511;
            int row = q >> 2, ch = q & 3;
            const __nv_bfloat16* src =
                (sel ? Al : Ah) + (size_t)(m0 + row) * C_ + k0 + ch * 8;
            cpasync16(sbase + (sel ? SA2_LO : SA2_HI) + row * RS2 + ch * 16, src);
        }
        // B: 2048 tasks (hi 1024 + lo 1024)
#pragma unroll
        for (int i = 0; i < 8; i++) {
            int p = tid + i * 256;
            int sel = p >> 10, q = p & 1023;
            int row = q >> 2, ch = q & 3;
            const __nv_bfloat16* src =
                (sel ? g_blo : g_bhi) + (size_t)(n0 + row) * C_ + k0 + ch * 8;
            cpasync16(sbase + (sel ? SB2_LO : SB2_HI) + row * RS2 + ch * 16, src);
        }
        CP_COMMIT();
    };

    prefetch(0);

    const int a_r = lane & 15;            // A ldsm row within 16
    const int a_c = (lane >> 4) * 8;      // A ldsm col half
    // B paired ldsm4: row = np*16 + (lane>>4)*8 + (lane&7), col half = (lane>>3)&1
    const int b_row = ((lane >> 4) * 8) + (lane & 7);
    const int b_ch  = ((lane >> 3) & 1) * 8;

    const int NCHUNK = C_ / 32;           // 32
    for (int chunk = 0; chunk < NCHUNK; chunk++) {
        if (chunk + 1 < NCHUNK) { prefetch(chunk + 1); CP_WAIT1(); }
        else                    { CP_WAIT0(); }
        __syncthreads();
        const uint32_t sbase = sb + (chunk & 1) * STAGE2;
#pragma unroll
        for (int ks = 0; ks < 2; ks++) {
            uint32_t fAh[4][4], fAl[4][4], fBh[4][4], fBl[4][4];
#pragma unroll
            for (int mi = 0; mi < 4; mi++) {
                uint32_t off = (uint32_t)((wm * 64 + mi * 16 + a_r) * RS2
                                          + (ks * 16 + a_c) * 2);
                ldsm4(fAh[mi], sbase + SA2_HI + off);
                ldsm4(fAl[mi], sbase + SA2_LO + off);
            }
#pragma unroll
            for (int np = 0; np < 4; np++) {
                uint32_t off = (uint32_t)((wn * 64 + np * 16 + b_row) * RS2
                                          + (ks * 16 + b_ch) * 2);
                ldsm4(fBh[np], sbase + SB2_HI + off);
                ldsm4(fBl[np], sbase + SB2_LO + off);
            }
#pragma unroll
            for (int mi = 0; mi < 4; mi++)
#pragma unroll
                for (int np = 0; np < 4; np++) {
                    // first n-octet of the pair: regs {0,1}
                    mma_bf16(acc[mi][2*np],   fAh[mi], &fBh[np][0]);
                    mma_bf16(acc[mi][2*np],   fAh[mi], &fBl[np][0]);
                    mma_bf16(acc[mi][2*np],   fAl[mi], &fBh[np][0]);
                    // second n-octet: regs {2,3}
                    mma_bf16(acc[mi][2*np+1], fAh[mi], &fBh[np][2]);
                    mma_bf16(acc[mi][2*np+1], fAh[mi], &fBl[np][2]);
                    mma_bf16(acc[mi][2*np+1], fAl[mi], &fBh[np][2]);
                }
        }
        __syncthreads();
    }

    // ---- epilogue ----
    const int g = lane >> 2, j = lane & 3;
    if (MODE == 0) {
        const int sec = n0 >> 10;               // 0=q 1=k 2=v (block inside one section)
        const int h = ((n0 & 1023) + wn * 64) >> 6;
        float* dst = (sec == 0) ? g_q : (sec == 1) ? g_k : g_v;
        const bool dorope = (sec < 2);
        const int nb = n0 + wn * 64;
#pragma unroll
        for (int mi = 0; mi < 4; mi++)
#pragma unroll
            for (int half = 0; half < 2; half++) {
                const int m = m0 + wm * 64 + mi * 16 + g + half * 8;
                const int bb = m >> 11, t = m & (T_ - 1);
                float* rowp = dst + ((size_t)(bb * NH_ + h) * T_ + t) * HD_;
#pragma unroll
                for (int ni = 0; ni < 4; ni++) {
                    const int d0 = ni * 8 + 2 * j;      // 0..30
                    float lo0 = acc[mi][ni][half * 2 + 0]     + bias[nb + d0];
                    float lo1 = acc[mi][ni][half * 2 + 1]     + bias[nb + d0 + 1];
                    float hi0 = acc[mi][ni + 4][half * 2 + 0] + bias[nb + d0 + 32];
                    float hi1 = acc[mi][ni + 4][half * 2 + 1] + bias[nb + d0 + 33];
                    if (dorope) {
                        float cs0 = g_cos[t * 32 + d0],     sn0 = g_sin[t * 32 + d0];
                        float cs1 = g_cos[t * 32 + d0 + 1], sn1 = g_sin[t * 32 + d0 + 1];
                        float a0 = lo0 * cs0 - hi0 * sn0;
                        float b0 = lo0 * sn0 + hi0 * cs0;
                        float a1 = lo1 * cs1 - hi1 * sn1;
                        float b1 = lo1 * sn1 + hi1 * cs1;
                        lo0 = a0; hi0 = b0; lo1 = a1; hi1 = b1;
                    }
                    *(float2*)(rowp + d0)      = make_float2(lo0, lo1);
                    *(float2*)(rowp + d0 + 32) = make_float2(hi0, hi1);
                }
            }
    } else {
#pragma unroll
        for (int mi = 0; mi < 4; mi++)
#pragma unroll
            for (int ni = 0; ni < 8; ni++)
#pragma unroll
                for (int half = 0; half < 2; half++) {
                    int m = m0 + wm * 64 + mi * 16 + g + half * 8;
                    int n = n0 + wn * 64 + ni * 8 + 2 * j;
                    float v0 = acc[mi][ni][half * 2 + 0] + bias[n];
                    float v1 = acc[mi][ni][half * 2 + 1] + bias[n + 1];
                    *(float2*)(out + (size_t)m * C_ + n) = make_float2(v0, v1);
                }
    }
}

// ============================================================
// Tensor-core flash attention (fp16 mma, online softmax, exp2)
//   (unchanged from R8 — passing at rel_err 7.7e-5)
// ============================================================
static constexpr int ARS = 144;                 // padded row bytes (64 fp16 + 8)
static constexpr int AQ_HI = 0;                 // Q staging (reused after)
static constexpr int AQ_LO = 18432;
static constexpr int AK    = 0;                 // K tile (after Q consumed)
static constexpr int AV_HI = 9216;
static constexpr int AV_LO = 18432;

__global__ __launch_bounds__(256)
void attn_mma_kernel()
{
    __shared__ __align__(128) char sm[36864];
    const uint32_t sb = smem_u32(sm);
    const int tid = threadIdx.x, lane = tid & 31, w = tid >> 5;
    const int bh = blockIdx.y;
    const int qt = gridDim.x - 1 - blockIdx.x;     // heavy tiles first
    const int q0 = qt * 128;

    const float* Qg = g_q + (size_t)bh * T_ * HD_;
    const float* Kg = g_k + (size_t)bh * T_ * HD_;
    const float* Vg = g_v + (size_t)bh * T_ * HD_;

    const float SCL = 0.125f * 1.4426950408889634f;  // 1/sqrt(64) * log2(e)

    // ---- stage Q (fp16 hi/lo, scaled) ----
#pragma unroll
    for (int i = 0; i < 8; i++) {
        int p = tid + i * 256;          // 2048 float4 slots = 128 rows x 16
        int row = p >> 4, c4 = (p & 15) * 4;
        float4 v = *(const float4*)(Qg + (size_t)(q0 + row) * HD_ + c4);
        v.x *= SCL; v.y *= SCL; v.z *= SCL; v.w *= SCL;
        __half2 h01 = __floats2half2_rn(v.x, v.y);
        __half2 h23 = __floats2half2_rn(v.z, v.w);
        float2 f01 = __half22float2(h01);
        float2 f23 = __half22float2(h23);
        uint32_t l01 = pkh2(v.x - f01.x, v.y - f01.y);
        uint32_t l23 = pkh2(v.z - f23.x, v.w - f23.y);
        uint32_t off = row * ARS + c4 * 2;
        *(uint2*)(sm + AQ_HI + off) = make_uint2(*(uint32_t*)&h01, *(uint32_t*)&h23);
        *(uint2*)(sm + AQ_LO + off) = make_uint2(l01, l23);
    }
    __syncthreads();

    // ---- Q fragments into registers ----
    const int a_r = lane & 15, a_c = (lane >> 4) * 8;
    uint32_t aQh[4][4], aQl[4][4];
#pragma unroll
    for (int ks = 0; ks < 4; ks++) {
        uint32_t off = (uint32_t)((w * 16 + a_r) * ARS + (ks * 16 + a_c) * 2);
        ldsm4(aQh[ks], sb + AQ_HI + off);
        ldsm4(aQl[ks], sb + AQ_LO + off);
    }
    __syncthreads();   // Q smem region now free for K/V

    float o[8][4];
#pragma unroll
    for (int n = 0; n < 8; n++)
#pragma unroll
        for (int c = 0; c < 4; c++) o[n][c] = 0.f;
    float mrow0 = -INFINITY, mrow1 = -INFINITY;
    float lrow0 = 0.f, lrow1 = 0.f;

    const int g = lane >> 2, j = lane & 3;
    const int b_r = lane & 7, b_c = ((lane >> 3) & 1) * 8;
    const int qw0 = q0 + w * 16;                  // warp's first query row
    const int ntiles = qt * 2 + 2;

    for (int kt = 0; kt < ntiles; kt++) {
        const int k0 = kt * 64;
        // ---- fill K (hi), V (hi/lo) tiles ----
#pragma unroll
        for (int i = 0; i < 4; i++) {
            int p = tid + i * 256;       // 1024 float4 slots = 64 rows x 16
            int row = p >> 4, c4 = (p & 15) * 4;
            uint32_t off = row * ARS + c4 * 2;
            float4 kv = *(const float4*)(Kg + (size_t)(k0 + row) * HD_ + c4);
            *(uint2*)(sm + AK + off) =
                make_uint2(pkh2(kv.x, kv.y), pkh2(kv.z, kv.w));
            float4 vv = *(const float4*)(Vg + (size_t)(k0 + row) * HD_ + c4);
            __half2 vh01 = __floats2half2_rn(vv.x, vv.y);
            __half2 vh23 = __floats2half2_rn(vv.z, vv.w);
            float2 f01 = __half22float2(vh01);
            float2 f23 = __half22float2(vh23);
            *(uint2*)(sm + AV_HI + off) =
                make_uint2(*(uint32_t*)&vh01, *(uint32_t*)&vh23);
            *(uint2*)(sm + AV_LO + off) =
                make_uint2(pkh2(vv.x - f01.x, vv.y - f01.y),
                           pkh2(vv.z - f23.x, vv.w - f23.y));
        }
        __syncthreads();

        if (k0 <= qw0 + 15) {   // warp has at least one unmasked row
            // ---- S = Q . K^T ----
            float c[8][4];
#pragma unroll
            for (int n = 0; n < 8; n++)
#pragma unroll
                for (int cc = 0; cc < 4; cc++) c[n][cc] = 0.f;
#pragma unroll
            for (int ks = 0; ks < 4; ks++) {
#pragma unroll
                for (int nn = 0; nn < 8; nn++) {
                    uint32_t bK[2];
                    ldsm2(bK, sb + AK + (uint32_t)((nn * 8 + b_r) * ARS
                                                   + (ks * 16 + b_c) * 2));
                    mma_f16(c[nn], aQh[ks], bK);
                    mma_f16(c[nn], aQl[ks], bK);
                }
            }
            // ---- causal mask ----
            if (k0 + 63 > qw0) {
                const int r0 = qw0 + g, r1 = qw0 + 8 + g;
#pragma unroll
                for (int nn = 0; nn < 8; nn++) {
                    int key = k0 + nn * 8 + 2 * j;
                    if (key     > r0) c[nn][0] = -INFINITY;
                    if (key + 1 > r0) c[nn][1] = -INFINITY;
                    if (key     > r1) c[nn][2] = -INFINITY;
                    if (key + 1 > r1) c[nn][3] = -INFINITY;
                }
            }
            // ---- row max (reduce over j lanes) ----
            float t0 = -INFINITY, t1 = -INFINITY;
#pragma unroll
            for (int nn = 0; nn < 8; nn++) {
                t0 = fmaxf(t0, fmaxf(c[nn][0], c[nn][1]));
                t1 = fmaxf(t1, fmaxf(c[nn][2], c[nn][3]));
            }
            t0 = fmaxf(t0, __shfl_xor_sync(0xffffffffu, t0, 1));
            t0 = fmaxf(t0, __shfl_xor_sync(0xffffffffu, t0, 2));
            t1 = fmaxf(t1, __shfl_xor_sync(0xffffffffu, t1, 1));
            t1 = fmaxf(t1, __shfl_xor_sync(0xffffffffu, t1, 2));
            float mn0 = fmaxf(mrow0, t0), mn1 = fmaxf(mrow1, t1);
            float al0 = exp2f(mrow0 - mn0), al1 = exp2f(mrow1 - mn1);
            mrow0 = mn0; mrow1 = mn1;
            lrow0 *= al0; lrow1 *= al1;
#pragma unroll
            for (int nn = 0; nn < 8; nn++) {
                o[nn][0] *= al0; o[nn][1] *= al0;
                o[nn][2] *= al1; o[nn][3] *= al1;
            }
            // ---- p = exp2(s-m), split fp16 hi/lo, build A frags ----
            uint32_t aPh[4][4], aPl[4][4];
#pragma unroll
            for (int nn = 0; nn < 8; nn++) {
                float p0 = exp2f(c[nn][0] - mn0);
                float p1 = exp2f(c[nn][1] - mn0);
                float p2 = exp2f(c[nn][2] - mn1);
                float p3 = exp2f(c[nn][3] - mn1);
                lrow0 += p0 + p1;
                lrow1 += p2 + p3;
                __half2 h01 = __floats2half2_rn(p0, p1);
                __half2 h23 = __floats2half2_rn(p2, p3);
                float2 f01 = __half22float2(h01);
                float2 f23 = __half22float2(h23);
                int ks = nn >> 1, sl = (nn & 1) * 2;
                aPh[ks][sl + 0] = *(uint32_t*)&h01;
                aPh[ks][sl + 1] = *(uint32_t*)&h23;
                aPl[ks][sl + 0] = pkh2(p0 - f01.x, p1 - f01.y);
                aPl[ks][sl + 1] = pkh2(p2 - f23.x, p3 - f23.y);
            }
            // ---- O += P . V ----
#pragma unroll
            for (int ks = 0; ks < 4; ks++) {
                uint32_t rbase = sb + (uint32_t)((ks * 16 + (lane & 15)) * ARS);
#pragma unroll
                for (int nn = 0; nn < 8; nn++) {
                    uint32_t bVh[2], bVl[2];
                    ldsm2t(bVh, rbase + AV_HI + nn * 16);
                    ldsm2t(bVl, rbase + AV_LO + nn * 16);
                    mma_f16(o[nn], aPh[ks], bVh);
                    mma_f16(o[nn], aPl[ks], bVh);
                    mma_f16(o[nn], aPh[ks], bVl);
                }
            }
        }
        __syncthreads();
    }

    // ---- finalize: reduce l over j lanes, normalize, write split ----
    lrow0 += __shfl_xor_sync(0xffffffffu, lrow0, 1);
    lrow0 += __shfl_xor_sync(0xffffffffu, lrow0, 2);
    lrow1 += __shfl_xor_sync(0xffffffffu, lrow1, 1);
    lrow1 += __shfl_xor_sync(0xffffffffu, lrow1, 2);
    float inv0 = 1.f / lrow0, inv1 = 1.f / lrow1;

    const int b = bh >> 4, h = bh & 15;
    const int m0r = q0 + w * 16 + g, m1r = m0r + 8;
    const size_t base0 = (size_t)(b * T_ + m0r) * C_ + h * 64;
    const size_t base1 = (size_t)(b * T_ + m1r) * C_ + h * 64;
#pragma unroll
    for (int nn = 0; nn < 8; nn++) {
        int d = nn * 8 + 2 * j;
        float v0 = o[nn][0] * inv0, v1 = o[nn][1] * inv0;
        float v2 = o[nn][2] * inv1, v3 = o[nn][3] * inv1;
        __nv_bfloat16 h0 = __float2bfloat16(v0), h1 = __float2bfloat16(v1);
        __nv_bfloat16 h2 = __float2bfloat16(v2), h3 = __float2bfloat16(v3);
        *(uint32_t*)(g_atthi + base0 + d) = pk2(h0, h1);
        *(uint32_t*)(g_attlo + base0 + d) =
            pk2(__float2bfloat16(v0 - __bfloat162float(h0)),
                __float2bfloat16(v1 - __bfloat162float(h1)));
        *(uint32_t*)(g_atthi + base1 + d) = pk2(h2, h3);
        *(uint32_t*)(g_attlo + base1 + d) =
            pk2(__float2bfloat16(v2 - __bfloat162float(h2)),
                __float2bfloat16(v3 - __bfloat162float(h3)));
    }
}

// ============================================================
// launcher
// ============================================================
extern "C" void kernel_launch(void* const* d_in, const int* in_sizes, int n_in,
                              void* d_out, int out_size)
{
    (void)in_sizes; (void)n_in;
    const float* x     = (const float*)d_in[0];
    const float* rnn   = (const float*)d_in[1];
    const float* Wqkv  = (const float*)d_in[2];
    const float* bqkv  = (const float*)d_in[3];
    const float* Wproj = (const float*)d_in[4];
    const float* bproj = (const float*)d_in[5];
    float* out = (float*)d_out;

    cudaFuncSetAttribute(mma_gemm_kernel<3 * C_, 0>,
                         cudaFuncAttributeMaxDynamicSharedMemorySize, SMEM_SZ2);
    cudaFuncSetAttribute(mma_gemm_kernel<C_, 1>,
                         cudaFuncAttributeMaxDynamicSharedMemorySize, SMEM_SZ2);

    rope_table_kernel<<<(T_ * 32 + 255) / 256, 256>>>();

    xconv_kernel<<<M_ * C_ / 4 / 256, 256>>>(x);
    wconv_kernel<<<dim3(3 * C_ / 32, C_ / 32), dim3(32, 8)>>>(Wqkv, 3 * C_);
    // QKV GEMM with fused RoPE epilogue
    mma_gemm_kernel<3 * C_, 0><<<dim3(12, 64), 256, SMEM_SZ2>>>(bqkv, nullptr);

    attn_mma_kernel<<<dim3(16, 64), 256>>>();

    wconv_kernel<<<dim3(C_ / 32, C_ / 32), dim3(32, 8)>>>(Wproj, C_);
    mma_gemm_kernel<C_, 1><<<dim3(4, 64), 256, SMEM_SZ2>>>(bproj, out);

    if (out_size >= (int)(M_ * C_ + B_ * C_)) {
        cudaMemcpyAsync(out + (size_t)M_ * C_, rnn,
                        (size_t)B_ * C_ * sizeof(float),
                        cudaMemcpyDeviceToDevice);
    }
}